// round 13
// baseline (speedup 1.0000x reference)
#include <cuda_runtime.h>
#include <cuda_fp16.h>
#include <math.h>
#include <stdint.h>

#define L_SEQ 8192
#define NB 2
#define NH 8
#define PD 32
#define DIM 256
#define M_ROWS (NB * L_SEQ)      // 16384
#define NHB (NB * NH)            // 16
#define CL 64                    // chunk length for scan
#define NCHUNK (L_SEQ / CL)      // 128

// ---------------- scratch (device globals; no allocations allowed) ----------
__device__ float g_pq[(size_t)NHB * L_SEQ * PD];      // phi(Y Wq^T), (nh,l,d)
__device__ float g_pk[(size_t)NHB * L_SEQ * PD];      // phi(X Wk^T)
__device__ float g_v [(size_t)NHB * L_SEQ * PD];      // X Wv^T
__device__ float g_coef [NHB * NCHUNK * 2 * CL];      // per-chunk c | cp
__device__ float g_tot  [NHB * 64 * NCHUNK];          // totals, [nh][slot][ch]
__device__ float g_carry[NHB * 64 * NCHUNK];          // carries, [nh][slot][ch]
__device__ __half g_Yh[(size_t)M_ROWS * DIM];         // fp16 copies
__device__ __half g_Xh[(size_t)M_ROWS * DIM];
__device__ __half g_Wh[3 * DIM * DIM];

// ---------------- helpers -----------------------------------------------------
__device__ __forceinline__ void mma_fp16(float c[4],
                                         uint32_t a0, uint32_t a1, uint32_t a2, uint32_t a3,
                                         uint32_t b0, uint32_t b1) {
    asm volatile(
        "mma.sync.aligned.m16n8k16.row.col.f32.f16.f16.f32 "
        "{%0,%1,%2,%3}, {%4,%5,%6,%7}, {%8,%9}, {%0,%1,%2,%3};"
        : "+f"(c[0]), "+f"(c[1]), "+f"(c[2]), "+f"(c[3])
        : "r"(a0), "r"(a1), "r"(a2), "r"(a3), "r"(b0), "r"(b1));
}

__device__ __forceinline__ void cp_async16(void* sdst, const void* gsrc) {
    uint32_t s = (uint32_t)__cvta_generic_to_shared(sdst);
    asm volatile("cp.async.cg.shared.global [%0], [%1], 16;" :: "r"(s), "l"(gsrc));
}

#define SW128(x) ((x) ^ (((x) >> 3) & 0x70))

// ---------------- Kernel 0: fp32 -> fp16 conversion ---------------------------
// blocks [0,4096): Y and X (1 float4 each per thread); [4096,4288): weights.
__global__ __launch_bounds__(256) void convert_kernel(
    const float* __restrict__ Y, const float* __restrict__ X,
    const float* __restrict__ Wq, const float* __restrict__ Wk,
    const float* __restrict__ Wv) {
    const int bx = blockIdx.x;
    const int tid = threadIdx.x;
    if (bx < 4096) {
        const size_t i4 = (size_t)bx * 256 + tid;       // float4 index
        float4 y = reinterpret_cast<const float4*>(Y)[i4];
        float4 x = reinterpret_cast<const float4*>(X)[i4];
        __half2 yh0 = __floats2half2_rn(y.x, y.y), yh1 = __floats2half2_rn(y.z, y.w);
        __half2 xh0 = __floats2half2_rn(x.x, x.y), xh1 = __floats2half2_rn(x.z, x.w);
        reinterpret_cast<uint2*>(g_Yh)[i4] =
            make_uint2(*reinterpret_cast<uint32_t*>(&yh0), *reinterpret_cast<uint32_t*>(&yh1));
        reinterpret_cast<uint2*>(g_Xh)[i4] =
            make_uint2(*reinterpret_cast<uint32_t*>(&xh0), *reinterpret_cast<uint32_t*>(&xh1));
    } else {
        const int wi = (bx - 4096) * 256 + tid;          // float4 index over 3 W
        const int wz = wi >> 14;                         // 16384 float4 per W
        const int wo = wi & 16383;
        const float* W = (wz == 0) ? Wq : ((wz == 1) ? Wk : Wv);
        float4 w = reinterpret_cast<const float4*>(W)[wo];
        __half2 h0 = __floats2half2_rn(w.x, w.y), h1 = __floats2half2_rn(w.z, w.w);
        reinterpret_cast<uint2*>(g_Wh)[wi] =
            make_uint2(*reinterpret_cast<uint32_t*>(&h0), *reinterpret_cast<uint32_t*>(&h1));
    }
}

// ---------------- Kernel 1: projections via fp16 mma.sync + cp.async ----------
// C[m][j] = sum_k A[m][k] * W[j][k]; phi for z<2; stored (n,h,l,d).
// Block tile 128(M) x 128(N), 8 warps (4x2), warp tile 32x64, K-tile 64 halves
// (128B rows, SW128 swizzle), 3-stage cp.async pipeline, 2 CTAs/SM.
#define NKT 4                    // 4 k-tiles of 64
#define STAGE_BYTES 32768        // A 16KB + B 16KB
#define PROJ_SMEM (3 * STAGE_BYTES)   // 98304

__global__ __launch_bounds__(256, 2) void proj_kernel(
    const float* __restrict__ dummy) {
    const int z = blockIdx.z;
    const __half* __restrict__ A = (z == 0) ? g_Yh : g_Xh;
    const __half* __restrict__ W = g_Wh + z * DIM * DIM;
    float* __restrict__ O = (z == 0) ? g_pq : ((z == 1) ? g_pk : g_v);

    const int rowStart = blockIdx.x * 128;
    const int colStart = blockIdx.y * 128;

    extern __shared__ char smem[];

    const int tid = threadIdx.x;
    const int lane = tid & 31;
    const int wid = tid >> 5;
    const int wm = wid & 3;           // warp row 0..3 (32 rows each)
    const int wn = wid >> 2;          // warp col 0..1 (64 cols each)
    const int g = lane >> 2;          // 0..7
    const int t = lane & 3;           // 0..3

    // staging: 1024 16B chunks per matrix per stage, 4 per thread
    const int cr0 = tid >> 3;         // +32*i
    const int ccc = tid & 7;          // 16B chunk in row

    float acc[2][8][4];
    #pragma unroll
    for (int mt = 0; mt < 2; mt++)
        #pragma unroll
        for (int nt = 0; nt < 8; nt++)
            #pragma unroll
            for (int i = 0; i < 4; i++) acc[mt][nt][i] = 0.f;

    auto stage_tile = [&](int kt, int st) {   // kt in halves
        char* As = smem + st * STAGE_BYTES;
        char* Bs = As + 16384;
        #pragma unroll
        for (int i = 0; i < 4; i++) {
            const int r = cr0 + 32 * i;
            cp_async16(As + SW128(r * 128 + ccc * 16),
                       &A[(size_t)(rowStart + r) * 256 + kt + ccc * 8]);
        }
        #pragma unroll
        for (int i = 0; i < 4; i++) {
            const int r = cr0 + 32 * i;
            cp_async16(Bs + SW128(r * 128 + ccc * 16),
                       &W[(size_t)(colStart + r) * 256 + kt + ccc * 8]);
        }
        asm volatile("cp.async.commit_group;" ::: "memory");
    };

    stage_tile(0, 0);
    stage_tile(64, 1);

    #pragma unroll
    for (int it = 0; it < NKT; it++) {
        if (it < NKT - 1) asm volatile("cp.async.wait_group 1;" ::: "memory");
        else              asm volatile("cp.async.wait_group 0;" ::: "memory");
        __syncthreads();
        if (it + 2 < NKT) stage_tile((it + 2) * 64, (it + 2) % 3);

        const char* As = smem + (it % 3) * STAGE_BYTES;
        const char* Bs = As + 16384;
        #pragma unroll
        for (int s = 0; s < 4; s++) {             // 4 k16 steps per k-tile
            const int kb = s * 32 + 4 * t;        // byte offset in row
            uint32_t a[2][4];
            #pragma unroll
            for (int mt = 0; mt < 2; mt++) {
                const int r = wm * 32 + mt * 16 + g;
                a[mt][0] = *reinterpret_cast<const uint32_t*>(As + SW128(r * 128 + kb));
                a[mt][1] = *reinterpret_cast<const uint32_t*>(As + SW128((r + 8) * 128 + kb));
                a[mt][2] = *reinterpret_cast<const uint32_t*>(As + SW128(r * 128 + kb + 16));
                a[mt][3] = *reinterpret_cast<const uint32_t*>(As + SW128((r + 8) * 128 + kb + 16));
            }
            uint32_t b[8][2];
            #pragma unroll
            for (int nt = 0; nt < 8; nt++) {
                const int nn = wn * 64 + nt * 8 + g;
                b[nt][0] = *reinterpret_cast<const uint32_t*>(Bs + SW128(nn * 128 + kb));
                b[nt][1] = *reinterpret_cast<const uint32_t*>(Bs + SW128(nn * 128 + kb + 16));
            }
            #pragma unroll
            for (int mt = 0; mt < 2; mt++)
                #pragma unroll
                for (int nt = 0; nt < 8; nt++)
                    mma_fp16(acc[mt][nt], a[mt][0], a[mt][1], a[mt][2], a[mt][3],
                             b[nt][0], b[nt][1]);
        }
        __syncthreads();
    }

    // --- epilogue: phi for z<2; write (n,h,l,d); cols 2t,2t+1 -> float2
    #pragma unroll
    for (int mt = 0; mt < 2; mt++) {
        #pragma unroll
        for (int nt = 0; nt < 8; nt++) {
            const int j0 = colStart + wn * 64 + nt * 8 + 2 * t;
            const int h = j0 >> 5;
            const int d = j0 & 31;
            #pragma unroll
            for (int half = 0; half < 2; half++) {
                const int m = rowStart + wm * 32 + mt * 16 + g + half * 8;
                const int n = m >> 13;
                const int l = m & (L_SEQ - 1);
                float v0 = acc[mt][nt][half * 2 + 0];
                float v1 = acc[mt][nt][half * 2 + 1];
                if (z < 2) {
                    v0 = (v0 > 0.f) ? (v0 + 1.f) : expf(v0);
                    v1 = (v1 > 0.f) ? (v1 + 1.f) : expf(v1);
                }
                size_t off = (((size_t)(n * NH + h) * L_SEQ) + l) * PD + d;
                *reinterpret_cast<float2*>(&O[off]) = make_float2(v0, v1);
            }
        }
    }
}

// ---------------- Kernel 2: coefficients + chunk totals (conflict-free) ------
__global__ __launch_bounds__(256) void totals_kernel() {
    const int nh = blockIdx.x;
    const int ch = blockIdx.y;
    const int s = ch * CL;
    const int tid = threadIdx.x;

    __shared__ float spk[CL * PD];
    __shared__ float sc [CL];
    __shared__ float scp[CL];
    __shared__ float s_part[4 * 64];

    const size_t base = (size_t)nh * L_SEQ * PD + (size_t)s * PD;
    for (int i = tid; i < CL * PD; i += 256)
        spk[i] = g_pk[base + i];

    // coefficients: 4 threads per position m (float4 global loads + shfl)
    {
        const int m = tid >> 2;
        const int p = tid & 3;
        const float* pq1 = &g_pq[base + (size_t)m * PD + p * 8];
        const float* vv  = &g_v [base + (size_t)m * PD + p * 8];
        float4 q1a = *reinterpret_cast<const float4*>(pq1);
        float4 q1b = *reinterpret_cast<const float4*>(pq1 + 4);
        float4 va  = *reinterpret_cast<const float4*>(vv);
        float4 vb  = *reinterpret_cast<const float4*>(vv + 4);
        float4 q0a = make_float4(0.f, 0.f, 0.f, 0.f), q0b = q0a;
        if (s + m > 0) {
            q0a = *reinterpret_cast<const float4*>(pq1 - PD);
            q0b = *reinterpret_cast<const float4*>(pq1 - PD + 4);
        }
        float dq[8] = { q1a.x - q0a.x, q1a.y - q0a.y, q1a.z - q0a.z, q1a.w - q0a.w,
                        q1b.x - q0b.x, q1b.y - q0b.y, q1b.z - q0b.z, q1b.w - q0b.w };
        float vl[8] = { va.x, va.y, va.z, va.w, vb.x, vb.y, vb.z, vb.w };
        float c = 0.f, cp = 0.f;
        #pragma unroll
        for (int j = 0; j < 8; j++) { c += dq[j] * vl[j]; cp += dq[j]; }
        c  += __shfl_xor_sync(0xffffffffu, c, 1);
        c  += __shfl_xor_sync(0xffffffffu, c, 2);
        cp += __shfl_xor_sync(0xffffffffu, cp, 1);
        cp += __shfl_xor_sync(0xffffffffu, cp, 2);
        if (p == 0) {
            sc[m] = c; scp[m] = cp;
            const int cb = (nh * NCHUNK + ch) * 2 * CL;
            g_coef[cb + m] = c;
            g_coef[cb + CL + m] = cp;
        }
    }
    __syncthreads();

    // conflict-free totals: slot = tid&63 (warp spans 32 d), gp = tid>>6
    const int slot = tid & 63;
    const int gp = tid >> 6;
    const int d = slot & 31;
    const float* coef = (slot < 32) ? sc : scp;
    float acc = 0.f;
    #pragma unroll
    for (int j = 0; j < 16; j++) {
        const int mm = gp * 16 + j;
        acc += coef[mm] * spk[mm * PD + d];
    }
    s_part[gp * 64 + slot] = acc;
    __syncthreads();
    if (tid < 64)
        g_tot[(nh * 64 + tid) * NCHUNK + ch] =
            s_part[tid] + s_part[64 + tid] + s_part[128 + tid] + s_part[192 + tid];
}

// ---------------- Kernel 3: parallel carries (warp per (nh,slot)) ------------
// One warp scans the 128 chunk totals of one (nh,slot): lane holds 4
// contiguous chunks (float4), register scan + shfl warp scan. Exclusive
// carries out. Math order identical to the old serial chain.
__global__ __launch_bounds__(256) void carry_kernel() {
    const int gw = (blockIdx.x * 256 + threadIdx.x) >> 5;   // 0..1023
    const int lane = threadIdx.x & 31;
    const int nh = gw >> 6;
    const int slot = gw & 63;

    const float4 v = reinterpret_cast<const float4*>(g_tot)[(nh * 64 + slot) * 32 + lane];
    const float s0 = v.x;
    const float s1 = s0 + v.y;
    const float s2 = s1 + v.z;
    const float s3 = s2 + v.w;

    // inclusive warp scan of per-lane totals
    float x = s3;
    #pragma unroll
    for (int off = 1; off < 32; off <<= 1) {
        float y = __shfl_up_sync(0xffffffffu, x, off);
        if (lane >= off) x += y;
    }
    const float excl = x - s3;

    float4 e;
    e.x = excl;
    e.y = excl + s0;
    e.z = excl + s1;
    e.w = excl + s2;
    reinterpret_cast<float4*>(g_carry)[(nh * 64 + slot) * 32 + lane] = e;
}

// ---------------- Kernel 4: local scan + carry + divide + output -------------
__global__ __launch_bounds__(256) void scanout_kernel(float* __restrict__ out) {
    const int nh = blockIdx.x;
    const int ch = blockIdx.y;
    const int tid = threadIdx.x;
    const int s = ch * CL;

    __shared__ float spk[CL * PD];
    __shared__ float sc [CL];
    __shared__ float scp[CL];
    __shared__ float s_part[4 * 64];
    __shared__ float s_pre[64 * (CL + 1)];

    const size_t base = (size_t)nh * L_SEQ * PD + (size_t)s * PD;
    for (int i = tid; i < CL * PD; i += 256)
        spk[i] = g_pk[base + i];
    {
        const int cb = (nh * NCHUNK + ch) * 2 * CL;
        if (tid < 2 * CL) ((tid < CL) ? sc : scp)[tid & (CL - 1)] = g_coef[cb + tid];
    }
    __syncthreads();

    // conflict-free local prefix: slot = tid&63, gp = tid>>6 (16 m each)
    const int slot = tid & 63;
    const int gp = tid >> 6;
    const int d = slot & 31;
    const float* coef = (slot < 32) ? sc : scp;
    float* pre = &s_pre[slot * (CL + 1)];
    float acc = 0.f;
    #pragma unroll
    for (int j = 0; j < 16; j++) {
        const int mm = gp * 16 + j;
        acc += coef[mm] * spk[mm * PD + d];
        pre[mm] = acc;
    }
    s_part[gp * 64 + slot] = acc;
    __syncthreads();
    float off = g_carry[(nh * 64 + slot) * NCHUNK + ch];
    if (gp > 0) off += s_part[slot];
    if (gp > 1) off += s_part[64 + slot];
    if (gp > 2) off += s_part[128 + slot];
    #pragma unroll
    for (int j = 0; j < 16; j++) pre[gp * 16 + j] += off;
    __syncthreads();

    // output: warp w handles rows m = w + 8*r, lane = d (coalesced 128B stores)
    {
        const int w = tid >> 5;
        const int lane = tid & 31;
        const int n = nh >> 3;
        const int h = nh & 7;
        #pragma unroll
        for (int r = 0; r < 8; r++) {
            const int mm = w + 8 * r;
            const float num = s_pre[lane * (CL + 1) + mm];
            const float den = s_pre[(32 + lane) * (CL + 1) + mm];
            const int l = s + mm;
            out[((size_t)n * L_SEQ + l) * DIM + h * PD + lane] = num / den;
        }
    }
}

// ---------------- launch ------------------------------------------------------
extern "C" void kernel_launch(void* const* d_in, const int* in_sizes, int n_in,
                              void* d_out, int out_size) {
    const float* Y  = (const float*)d_in[0];
    const float* X  = (const float*)d_in[1];
    const float* Wq = (const float*)d_in[2];
    const float* Wk = (const float*)d_in[3];
    const float* Wv = (const float*)d_in[4];
    // d_in[5] = mask; always 1 (causal) per problem setup
    float* out = (float*)d_out;

    cudaFuncSetAttribute(proj_kernel,
                         cudaFuncAttributeMaxDynamicSharedMemorySize, PROJ_SMEM);

    convert_kernel<<<4096 + 192, 256>>>(Y, X, Wq, Wk, Wv);

    dim3 pg(M_ROWS / 128, DIM / 128, 3);
    proj_kernel<<<pg, 256, PROJ_SMEM>>>(nullptr);

    dim3 sg(NHB, NCHUNK);
    totals_kernel<<<sg, 256>>>();

    carry_kernel<<<128, 256>>>();

    scanout_kernel<<<sg, 256>>>(out);
}

// round 15
// speedup vs baseline: 1.5066x; 1.5066x over previous
#include <cuda_runtime.h>
#include <cuda_fp16.h>
#include <math.h>
#include <stdint.h>

#define L_SEQ 8192
#define NB 2
#define NH 8
#define PD 32
#define DIM 256
#define M_ROWS (NB * L_SEQ)      // 16384
#define NHB (NB * NH)            // 16
#define CL 64                    // chunk length for scan
#define NCHUNK (L_SEQ / CL)      // 128

// ---------------- scratch (device globals; no allocations allowed) ----------
__device__ float  g_pq[(size_t)NHB * L_SEQ * PD];     // phi(Y Wq^T), fp32 (cancellation-sensitive)
__device__ __half g_pkh[(size_t)NHB * L_SEQ * PD];    // phi(X Wk^T), fp16
__device__ __half g_vh [(size_t)NHB * L_SEQ * PD];    // X Wv^T, fp16
__device__ float g_coef [NHB * NCHUNK * 2 * CL];      // per-chunk c | cp
__device__ float g_tot  [NHB * 64 * NCHUNK];          // totals, [nh][slot][ch]
__device__ float g_carry[NHB * 64 * NCHUNK];          // carries, [nh][slot][ch]
__device__ __half g_Yh[(size_t)M_ROWS * DIM];         // fp16 copies
__device__ __half g_Xh[(size_t)M_ROWS * DIM];
__device__ __half g_Wh[3 * DIM * DIM];

// ---------------- helpers -----------------------------------------------------
__device__ __forceinline__ void mma_fp16(float c[4],
                                         uint32_t a0, uint32_t a1, uint32_t a2, uint32_t a3,
                                         uint32_t b0, uint32_t b1) {
    asm volatile(
        "mma.sync.aligned.m16n8k16.row.col.f32.f16.f16.f32 "
        "{%0,%1,%2,%3}, {%4,%5,%6,%7}, {%8,%9}, {%0,%1,%2,%3};"
        : "+f"(c[0]), "+f"(c[1]), "+f"(c[2]), "+f"(c[3])
        : "r"(a0), "r"(a1), "r"(a2), "r"(a3), "r"(b0), "r"(b1));
}

__device__ __forceinline__ void cp_async16(void* sdst, const void* gsrc) {
    uint32_t s = (uint32_t)__cvta_generic_to_shared(sdst);
    asm volatile("cp.async.cg.shared.global [%0], [%1], 16;" :: "r"(s), "l"(gsrc));
}

#define SW128(x) ((x) ^ (((x) >> 3) & 0x70))

// ---------------- Kernel 0: fp32 -> fp16 conversion ---------------------------
// blocks [0,4096): Y and X (1 float4 each per thread); [4096,4288): weights.
__global__ __launch_bounds__(256) void convert_kernel(
    const float* __restrict__ Y, const float* __restrict__ X,
    const float* __restrict__ Wq, const float* __restrict__ Wk,
    const float* __restrict__ Wv) {
    const int bx = blockIdx.x;
    const int tid = threadIdx.x;
    if (bx < 4096) {
        const size_t i4 = (size_t)bx * 256 + tid;       // float4 index
        float4 y = reinterpret_cast<const float4*>(Y)[i4];
        float4 x = reinterpret_cast<const float4*>(X)[i4];
        __half2 yh0 = __floats2half2_rn(y.x, y.y), yh1 = __floats2half2_rn(y.z, y.w);
        __half2 xh0 = __floats2half2_rn(x.x, x.y), xh1 = __floats2half2_rn(x.z, x.w);
        reinterpret_cast<uint2*>(g_Yh)[i4] =
            make_uint2(*reinterpret_cast<uint32_t*>(&yh0), *reinterpret_cast<uint32_t*>(&yh1));
        reinterpret_cast<uint2*>(g_Xh)[i4] =
            make_uint2(*reinterpret_cast<uint32_t*>(&xh0), *reinterpret_cast<uint32_t*>(&xh1));
    } else {
        const int wi = (bx - 4096) * 256 + tid;          // float4 index over 3 W
        const int wz = wi >> 14;                         // 16384 float4 per W
        const int wo = wi & 16383;
        const float* W = (wz == 0) ? Wq : ((wz == 1) ? Wk : Wv);
        float4 w = reinterpret_cast<const float4*>(W)[wo];
        __half2 h0 = __floats2half2_rn(w.x, w.y), h1 = __floats2half2_rn(w.z, w.w);
        reinterpret_cast<uint2*>(g_Wh)[wi] =
            make_uint2(*reinterpret_cast<uint32_t*>(&h0), *reinterpret_cast<uint32_t*>(&h1));
    }
}

// ---------------- Kernel 1: projections via fp16 mma.sync + cp.async ----------
// C[m][j] = sum_k A[m][k] * W[j][k]; phi for z<2; stored (n,h,l,d).
// z=0 -> g_pq fp32; z=1 -> g_pkh fp16; z=2 -> g_vh fp16.
// Block tile 128(M) x 128(N), 8 warps (4x2), warp tile 32x64, K-tile 64 halves
// (128B rows, SW128 swizzle), 3-stage cp.async pipeline.
#define NKT 4                    // 4 k-tiles of 64
#define STAGE_BYTES 32768        // A 16KB + B 16KB
#define PROJ_SMEM (3 * STAGE_BYTES)   // 98304

__global__ __launch_bounds__(256) void proj_kernel(
    const float* __restrict__ dummy) {
    const int z = blockIdx.z;
    const __half* __restrict__ A = (z == 0) ? g_Yh : g_Xh;
    const __half* __restrict__ W = g_Wh + z * DIM * DIM;

    const int rowStart = blockIdx.x * 128;
    const int colStart = blockIdx.y * 128;

    extern __shared__ char smem[];

    const int tid = threadIdx.x;
    const int lane = tid & 31;
    const int wid = tid >> 5;
    const int wm = wid & 3;           // warp row 0..3 (32 rows each)
    const int wn = wid >> 2;          // warp col 0..1 (64 cols each)
    const int g = lane >> 2;          // 0..7
    const int t = lane & 3;           // 0..3

    // staging: 1024 16B chunks per matrix per stage, 4 per thread
    const int cr0 = tid >> 3;         // +32*i
    const int ccc = tid & 7;          // 16B chunk in row

    float acc[2][8][4];
    #pragma unroll
    for (int mt = 0; mt < 2; mt++)
        #pragma unroll
        for (int nt = 0; nt < 8; nt++)
            #pragma unroll
            for (int i = 0; i < 4; i++) acc[mt][nt][i] = 0.f;

    auto stage_tile = [&](int kt, int st) {   // kt in halves
        char* As = smem + st * STAGE_BYTES;
        char* Bs = As + 16384;
        #pragma unroll
        for (int i = 0; i < 4; i++) {
            const int r = cr0 + 32 * i;
            cp_async16(As + SW128(r * 128 + ccc * 16),
                       &A[(size_t)(rowStart + r) * 256 + kt + ccc * 8]);
        }
        #pragma unroll
        for (int i = 0; i < 4; i++) {
            const int r = cr0 + 32 * i;
            cp_async16(Bs + SW128(r * 128 + ccc * 16),
                       &W[(size_t)(colStart + r) * 256 + kt + ccc * 8]);
        }
        asm volatile("cp.async.commit_group;" ::: "memory");
    };

    stage_tile(0, 0);
    stage_tile(64, 1);

    #pragma unroll
    for (int it = 0; it < NKT; it++) {
        if (it < NKT - 1) asm volatile("cp.async.wait_group 1;" ::: "memory");
        else              asm volatile("cp.async.wait_group 0;" ::: "memory");
        __syncthreads();
        if (it + 2 < NKT) stage_tile((it + 2) * 64, (it + 2) % 3);

        const char* As = smem + (it % 3) * STAGE_BYTES;
        const char* Bs = As + 16384;
        #pragma unroll
        for (int s = 0; s < 4; s++) {             // 4 k16 steps per k-tile
            const int kb = s * 32 + 4 * t;        // byte offset in row
            uint32_t a[2][4];
            #pragma unroll
            for (int mt = 0; mt < 2; mt++) {
                const int r = wm * 32 + mt * 16 + g;
                a[mt][0] = *reinterpret_cast<const uint32_t*>(As + SW128(r * 128 + kb));
                a[mt][1] = *reinterpret_cast<const uint32_t*>(As + SW128((r + 8) * 128 + kb));
                a[mt][2] = *reinterpret_cast<const uint32_t*>(As + SW128(r * 128 + kb + 16));
                a[mt][3] = *reinterpret_cast<const uint32_t*>(As + SW128((r + 8) * 128 + kb + 16));
            }
            uint32_t b[8][2];
            #pragma unroll
            for (int nt = 0; nt < 8; nt++) {
                const int nn = wn * 64 + nt * 8 + g;
                b[nt][0] = *reinterpret_cast<const uint32_t*>(Bs + SW128(nn * 128 + kb));
                b[nt][1] = *reinterpret_cast<const uint32_t*>(Bs + SW128(nn * 128 + kb + 16));
            }
            #pragma unroll
            for (int mt = 0; mt < 2; mt++)
                #pragma unroll
                for (int nt = 0; nt < 8; nt++)
                    mma_fp16(acc[mt][nt], a[mt][0], a[mt][1], a[mt][2], a[mt][3],
                             b[nt][0], b[nt][1]);
        }
        __syncthreads();
    }

    // --- epilogue: phi for z<2; write (n,h,l,d)
    #pragma unroll
    for (int mt = 0; mt < 2; mt++) {
        #pragma unroll
        for (int nt = 0; nt < 8; nt++) {
            const int j0 = colStart + wn * 64 + nt * 8 + 2 * t;
            const int h = j0 >> 5;
            const int d = j0 & 31;
            #pragma unroll
            for (int half = 0; half < 2; half++) {
                const int m = rowStart + wm * 32 + mt * 16 + g + half * 8;
                const int n = m >> 13;
                const int l = m & (L_SEQ - 1);
                float v0 = acc[mt][nt][half * 2 + 0];
                float v1 = acc[mt][nt][half * 2 + 1];
                if (z < 2) {
                    v0 = (v0 > 0.f) ? (v0 + 1.f) : expf(v0);
                    v1 = (v1 > 0.f) ? (v1 + 1.f) : expf(v1);
                }
                size_t off = (((size_t)(n * NH + h) * L_SEQ) + l) * PD + d;
                if (z == 0) {
                    *reinterpret_cast<float2*>(&g_pq[off]) = make_float2(v0, v1);
                } else {
                    __half2 hv = __floats2half2_rn(v0, v1);
                    __half* dst = (z == 1) ? g_pkh : g_vh;
                    *reinterpret_cast<__half2*>(&dst[off]) = hv;
                }
            }
        }
    }
}

// ---------------- Kernel 2: coefficients + chunk totals (conflict-free) ------
__global__ __launch_bounds__(256) void totals_kernel() {
    const int nh = blockIdx.x;
    const int ch = blockIdx.y;
    const int s = ch * CL;
    const int tid = threadIdx.x;

    __shared__ float spk[CL * PD];
    __shared__ float sc [CL];
    __shared__ float scp[CL];
    __shared__ float s_part[4 * 64];

    const size_t base = (size_t)nh * L_SEQ * PD + (size_t)s * PD;
    // pk (fp16) -> smem fp32
    for (int i = tid; i < CL * PD / 2; i += 256) {
        __half2 h = reinterpret_cast<const __half2*>(g_pkh + base)[i];
        float2 f = __half22float2(h);
        *reinterpret_cast<float2*>(&spk[2 * i]) = f;
    }

    // coefficients: 4 threads per position m
    {
        const int m = tid >> 2;
        const int p = tid & 3;
        const float* pq1 = &g_pq[base + (size_t)m * PD + p * 8];
        const __half* vh = &g_vh[base + (size_t)m * PD + p * 8];
        float4 q1a = *reinterpret_cast<const float4*>(pq1);
        float4 q1b = *reinterpret_cast<const float4*>(pq1 + 4);
        uint4 vr = *reinterpret_cast<const uint4*>(vh);
        float2 f0 = __half22float2(*reinterpret_cast<__half2*>(&vr.x));
        float2 f1 = __half22float2(*reinterpret_cast<__half2*>(&vr.y));
        float2 f2 = __half22float2(*reinterpret_cast<__half2*>(&vr.z));
        float2 f3 = __half22float2(*reinterpret_cast<__half2*>(&vr.w));
        float4 q0a = make_float4(0.f, 0.f, 0.f, 0.f), q0b = q0a;
        if (s + m > 0) {
            q0a = *reinterpret_cast<const float4*>(pq1 - PD);
            q0b = *reinterpret_cast<const float4*>(pq1 - PD + 4);
        }
        float dq[8] = { q1a.x - q0a.x, q1a.y - q0a.y, q1a.z - q0a.z, q1a.w - q0a.w,
                        q1b.x - q0b.x, q1b.y - q0b.y, q1b.z - q0b.z, q1b.w - q0b.w };
        float vl[8] = { f0.x, f0.y, f1.x, f1.y, f2.x, f2.y, f3.x, f3.y };
        float c = 0.f, cp = 0.f;
        #pragma unroll
        for (int j = 0; j < 8; j++) { c += dq[j] * vl[j]; cp += dq[j]; }
        c  += __shfl_xor_sync(0xffffffffu, c, 1);
        c  += __shfl_xor_sync(0xffffffffu, c, 2);
        cp += __shfl_xor_sync(0xffffffffu, cp, 1);
        cp += __shfl_xor_sync(0xffffffffu, cp, 2);
        if (p == 0) {
            sc[m] = c; scp[m] = cp;
            const int cb = (nh * NCHUNK + ch) * 2 * CL;
            g_coef[cb + m] = c;
            g_coef[cb + CL + m] = cp;
        }
    }
    __syncthreads();

    // conflict-free totals: slot = tid&63 (warp spans 32 d), gp = tid>>6
    const int slot = tid & 63;
    const int gp = tid >> 6;
    const int d = slot & 31;
    const float* coef = (slot < 32) ? sc : scp;
    float acc = 0.f;
    #pragma unroll
    for (int j = 0; j < 16; j++) {
        const int mm = gp * 16 + j;
        acc += coef[mm] * spk[mm * PD + d];
    }
    s_part[gp * 64 + slot] = acc;
    __syncthreads();
    if (tid < 64)
        g_tot[(nh * 64 + tid) * NCHUNK + ch] =
            s_part[tid] + s_part[64 + tid] + s_part[128 + tid] + s_part[192 + tid];
}

// ---------------- Kernel 3: parallel carries (warp per (nh,slot)) ------------
__global__ __launch_bounds__(256) void carry_kernel() {
    const int gw = (blockIdx.x * 256 + threadIdx.x) >> 5;   // 0..1023
    const int lane = threadIdx.x & 31;
    const int nh = gw >> 6;
    const int slot = gw & 63;

    const float4 v = reinterpret_cast<const float4*>(g_tot)[(nh * 64 + slot) * 32 + lane];
    const float s0 = v.x;
    const float s1 = s0 + v.y;
    const float s2 = s1 + v.z;
    const float s3 = s2 + v.w;

    // inclusive warp scan of per-lane totals
    float x = s3;
    #pragma unroll
    for (int off = 1; off < 32; off <<= 1) {
        float y = __shfl_up_sync(0xffffffffu, x, off);
        if (lane >= off) x += y;
    }
    const float excl = x - s3;

    float4 e;
    e.x = excl;
    e.y = excl + s0;
    e.z = excl + s1;
    e.w = excl + s2;
    reinterpret_cast<float4*>(g_carry)[(nh * 64 + slot) * 32 + lane] = e;
}

// ---------------- Kernel 4: local scan + carry + divide + output -------------
__global__ __launch_bounds__(256) void scanout_kernel(float* __restrict__ out) {
    const int nh = blockIdx.x;
    const int ch = blockIdx.y;
    const int tid = threadIdx.x;
    const int s = ch * CL;

    __shared__ float spk[CL * PD];
    __shared__ float sc [CL];
    __shared__ float scp[CL];
    __shared__ float s_part[4 * 64];
    __shared__ float s_pre[64 * (CL + 1)];

    const size_t base = (size_t)nh * L_SEQ * PD + (size_t)s * PD;
    for (int i = tid; i < CL * PD / 2; i += 256) {
        __half2 h = reinterpret_cast<const __half2*>(g_pkh + base)[i];
        float2 f = __half22float2(h);
        *reinterpret_cast<float2*>(&spk[2 * i]) = f;
    }
    {
        const int cb = (nh * NCHUNK + ch) * 2 * CL;
        if (tid < 2 * CL) ((tid < CL) ? sc : scp)[tid & (CL - 1)] = g_coef[cb + tid];
    }
    __syncthreads();

    // conflict-free local prefix: slot = tid&63, gp = tid>>6 (16 m each)
    const int slot = tid & 63;
    const int gp = tid >> 6;
    const int d = slot & 31;
    const float* coef = (slot < 32) ? sc : scp;
    float* pre = &s_pre[slot * (CL + 1)];
    float acc = 0.f;
    #pragma unroll
    for (int j = 0; j < 16; j++) {
        const int mm = gp * 16 + j;
        acc += coef[mm] * spk[mm * PD + d];
        pre[mm] = acc;
    }
    s_part[gp * 64 + slot] = acc;
    __syncthreads();
    float off = g_carry[(nh * 64 + slot) * NCHUNK + ch];
    if (gp > 0) off += s_part[slot];
    if (gp > 1) off += s_part[64 + slot];
    if (gp > 2) off += s_part[128 + slot];
    #pragma unroll
    for (int j = 0; j < 16; j++) pre[gp * 16 + j] += off;
    __syncthreads();

    // output: warp w handles rows m = w + 8*r, lane = d (coalesced 128B stores)
    {
        const int w = tid >> 5;
        const int lane = tid & 31;
        const int n = nh >> 3;
        const int h = nh & 7;
        #pragma unroll
        for (int r = 0; r < 8; r++) {
            const int mm = w + 8 * r;
            const float num = s_pre[lane * (CL + 1) + mm];
            const float den = s_pre[(32 + lane) * (CL + 1) + mm];
            const int l = s + mm;
            out[((size_t)n * L_SEQ + l) * DIM + h * PD + lane] = num / den;
        }
    }
}

// ---------------- launch ------------------------------------------------------
extern "C" void kernel_launch(void* const* d_in, const int* in_sizes, int n_in,
                              void* d_out, int out_size) {
    const float* Y  = (const float*)d_in[0];
    const float* X  = (const float*)d_in[1];
    const float* Wq = (const float*)d_in[2];
    const float* Wk = (const float*)d_in[3];
    const float* Wv = (const float*)d_in[4];
    // d_in[5] = mask; always 1 (causal) per problem setup
    float* out = (float*)d_out;

    cudaFuncSetAttribute(proj_kernel,
                         cudaFuncAttributeMaxDynamicSharedMemorySize, PROJ_SMEM);

    convert_kernel<<<4096 + 192, 256>>>(Y, X, Wq, Wk, Wv);

    dim3 pg(M_ROWS / 128, DIM / 128, 3);
    proj_kernel<<<pg, 256, PROJ_SMEM>>>(nullptr);

    dim3 sg(NHB, NCHUNK);
    totals_kernel<<<sg, 256>>>();

    carry_kernel<<<128, 256>>>();

    scanout_kernel<<<sg, 256>>>(out);
}